// round 16
// baseline (speedup 1.0000x reference)
#include <cuda_runtime.h>
#include <cuda_fp16.h>
#include <cstdint>

// VectorQuantizer fwd: N=8192 tokens, V=8192 codes, C=32.
// S = zfn@en^T via mma.sync.m16n8k16 fp16, 3-product fp16 split:
//   u = z1e1 + 2^-12*( z1*(e2*2^12) + (z2*2^12)*e1 )  ~ fp32-exact
// B stores [e1 | e2'] (K=64); z2'*e1 reuses e1 ldmatrix frags; zero-C init.
// TILE=128 codes (two 64-col passes/tile): half the barriers/stages of TILE=64.

#define N_TOK 8192
#define V_CODES 8192
#define C_DIM 32
#define YS 4                    // grid.y splits
#define VS 4
#define VPB (V_CODES / YS)      // 2048 codes per block
#define TILE 128
#define NTIL (VPB / TILE)       // 16 tiles
#define TOKB 128
#define KA 32                   // u32 per A row: [z1 | z2'] fp16x2
#define KB 32                   // u32 per B row: [e1 | e2'] fp16x2
#define RSW 36                  // smem row stride in u32 (144B, bank-clean)
#define BUF_BYTES (TILE * RSW * 4)     // 18432
#define SMEM_DYN (3 * BUF_BYTES + 4 * TILE * 4 + 64)
#define L2E 1.4426950408889634f
#define LN2 0.6931471805599453f
#define L2EPS 1e-12f
#define RSCALE 4096.0f
#define RINV 0.000244140625f    // 2^-12

typedef unsigned int u32;

__device__ __align__(16) u32   g_abf[N_TOK * KA];    // A rows: [z1 | z2'] fp16x2
__device__ __align__(16) u32   g_bbf[V_CODES * KB];  // B rows: [e1 | e2'] fp16x2
__device__ __align__(16) float g_en[V_CODES * C_DIM];
__device__ __align__(16) float g_esq2[V_CODES];      // esq * log2e
__device__ __align__(16) float g_zfn[N_TOK * C_DIM];
__device__ float g_pd[N_TOK * VS];
__device__ int   g_pi[N_TOK * VS];
__device__ float g_ps[N_TOK * VS];
__device__ float g_blk[128][2];
__device__ int   g_cnt;

__device__ __forceinline__ u32 smem_u32(const void* p) {
    u32 a;
    asm("{ .reg .u64 t; cvta.to.shared.u64 t, %1; cvt.u32.u64 %0, t; }" : "=r"(a) : "l"(p));
    return a;
}
__device__ __forceinline__ void cpa16(u32 s, const void* g) {
    asm volatile("cp.async.cg.shared.global [%0], [%1], 16;" :: "r"(s), "l"(g));
}
__device__ __forceinline__ void cpa_commit() { asm volatile("cp.async.commit_group;" ::: "memory"); }
template <int N> __device__ __forceinline__ void cpa_wait() {
    asm volatile("cp.async.wait_group %0;" :: "n"(N) : "memory");
}
__device__ __forceinline__ void ldm_x4(u32& r0, u32& r1, u32& r2, u32& r3, u32 addr) {
    asm volatile("ldmatrix.sync.aligned.m8n8.x4.shared.b16 {%0,%1,%2,%3}, [%4];"
                 : "=r"(r0), "=r"(r1), "=r"(r2), "=r"(r3) : "r"(addr));
}
// accumulate: D += A*B
__device__ __forceinline__ void mma16816(float* c, const u32* a, u32 b0, u32 b1) {
    asm volatile("mma.sync.aligned.m16n8k16.row.col.f32.f16.f16.f32 "
                 "{%0,%1,%2,%3}, {%4,%5,%6,%7}, {%8,%9}, {%0,%1,%2,%3};"
                 : "+f"(c[0]), "+f"(c[1]), "+f"(c[2]), "+f"(c[3])
                 : "r"(a[0]), "r"(a[1]), "r"(a[2]), "r"(a[3]), "r"(b0), "r"(b1));
}
// initialize: D = A*B (C = 0)
__device__ __forceinline__ void mma16816_zc(float* d, const u32* a, u32 b0, u32 b1) {
    asm volatile("mma.sync.aligned.m16n8k16.row.col.f32.f16.f16.f32 "
                 "{%0,%1,%2,%3}, {%4,%5,%6,%7}, {%8,%9}, {%10,%11,%12,%13};"
                 : "=f"(d[0]), "=f"(d[1]), "=f"(d[2]), "=f"(d[3])
                 : "r"(a[0]), "r"(a[1]), "r"(a[2]), "r"(a[3]), "r"(b0), "r"(b1),
                   "f"(0.f), "f"(0.f), "f"(0.f), "f"(0.f));
}
__device__ __forceinline__ float ex2f(float x) {
    float r; asm("ex2.approx.f32 %0, %1;" : "=f"(r) : "f"(x)); return r;
}
__device__ __forceinline__ float lg2f(float x) {
    float r; asm("lg2.approx.f32 %0, %1;" : "=f"(r) : "f"(x)); return r;
}
__device__ __forceinline__ u32 packh(__half a, __half b) {
    __half2 hh = __halves2half2(a, b);
    return *(u32*)&hh;
}

// ---- kernel 1: prep (256 blocks x 256 threads; 4 threads per row) ----------
__global__ void prep(const float* __restrict__ z, const float* __restrict__ emb) {
    int tid = threadIdx.x;
    int qt = tid & 3;            // quarter: channels qt*8 .. qt*8+7
    float vv[8];
    __half h1[8], h2[8];

    if (blockIdx.x < 128) {
        int r = blockIdx.x * 64 + (tid >> 2);
        const float4* src = (const float4*)(emb + r * C_DIM + qt * 8);
        float4 v0 = src[0], v1 = src[1];
        float ss = v0.x * v0.x + v0.y * v0.y + v0.z * v0.z + v0.w * v0.w
                 + v1.x * v1.x + v1.y * v1.y + v1.z * v1.z + v1.w * v1.w;
        ss += __shfl_xor_sync(~0u, ss, 1, 4);
        ss += __shfl_xor_sync(~0u, ss, 2, 4);
        float rcp = 1.0f / fmaxf(sqrtf(ss), L2EPS);
        vv[0] = v0.x * rcp; vv[1] = v0.y * rcp; vv[2] = v0.z * rcp; vv[3] = v0.w * rcp;
        vv[4] = v1.x * rcp; vv[5] = v1.y * rcp; vv[6] = v1.z * rcp; vv[7] = v1.w * rcp;
        float4* dst = (float4*)(g_en + r * C_DIM + qt * 8);
        dst[0] = make_float4(vv[0], vv[1], vv[2], vv[3]);
        dst[1] = make_float4(vv[4], vv[5], vv[6], vv[7]);
        float es = 0.f;
#pragma unroll
        for (int j = 0; j < 8; j++) es = fmaf(vv[j], vv[j], es);
        es += __shfl_xor_sync(~0u, es, 1, 4);
        es += __shfl_xor_sync(~0u, es, 2, 4);
        if (qt == 0) g_esq2[r] = es * L2E;
#pragma unroll
        for (int j = 0; j < 8; j++) {
            h1[j] = __float2half_rn(vv[j]);
            h2[j] = __float2half_rn((vv[j] - __half2float(h1[j])) * RSCALE);
        }
        const __half* segs[2] = { h1, h2 };           // B: e1 | e2'
        u32* brow = g_bbf + (size_t)r * KB + qt * 4;
#pragma unroll
        for (int s = 0; s < 2; s++)
#pragma unroll
            for (int p = 0; p < 4; p++)
                brow[s * 16 + p] = packh(segs[s][2 * p], segs[s][2 * p + 1]);
    } else {
        int n = (blockIdx.x - 128) * 64 + (tid >> 2);
        int b = n >> 10, hw = n & 1023;
        const float* zp = z + b * (C_DIM * 1024) + (qt * 8) * 1024 + hw;
        float ss = 0.f;
#pragma unroll
        for (int j = 0; j < 8; j++) { vv[j] = zp[j * 1024]; ss = fmaf(vv[j], vv[j], ss); }
        ss += __shfl_xor_sync(~0u, ss, 1, 4);
        ss += __shfl_xor_sync(~0u, ss, 2, 4);
        float rcp = 1.0f / fmaxf(sqrtf(ss), L2EPS);
        float4* dst = (float4*)(g_zfn + n * C_DIM + qt * 8);
        dst[0] = make_float4(vv[0] * rcp, vv[1] * rcp, vv[2] * rcp, vv[3] * rcp);
        dst[1] = make_float4(vv[4] * rcp, vv[5] * rcp, vv[6] * rcp, vv[7] * rcp);
        float rs = rcp * L2E;
#pragma unroll
        for (int j = 0; j < 8; j++) {
            float zs = vv[j] * rs;
            h1[j] = __float2half_rn(zs);
            h2[j] = __float2half_rn((zs - __half2float(h1[j])) * RSCALE);
        }
        const __half* segs[2] = { h1, h2 };           // A: z1 | z2'
        u32* arow = g_abf + (size_t)n * KA + qt * 4;
#pragma unroll
        for (int s = 0; s < 2; s++)
#pragma unroll
            for (int p = 0; p < 4; p++)
                arow[s * 16 + p] = packh(segs[s][2 * p], segs[s][2 * p + 1]);
    }
}

// ---- kernel 2: HMMA similarity scan, TILE=128, two 64-col passes -----------
// grid (64, 4), 256 threads, 2 CTAs/SM. 8 warps, warp = 16 token rows.
__global__ __launch_bounds__(256, 2) void vq_main() {
    extern __shared__ __align__(16) char dsm[];
    u32 sb = smem_u32(dsm);                      // [3][TILE*RSW] u32
    float* sE = (float*)(dsm + 3 * BUF_BYTES);   // [4][TILE]

    int tid = threadIdx.x;
    int w = tid >> 5, lane = tid & 31;
    int g = lane >> 2, tg = lane & 3;
    int Rb = blockIdx.x * TOKB + w * 16;
    int vbase = blockIdx.y * VPB;

    // A fragments: z1 (k-steps 0,1) and z2' (k-steps 0,1), loaded once.
    u32 af1[2][4], af2[2][4];
    {
        const u32* A0 = g_abf + (size_t)(Rb + g) * KA;
        const u32* A8 = g_abf + (size_t)(Rb + g + 8) * KA;
#pragma unroll
        for (int k = 0; k < 2; k++) {
            af1[k][0] = A0[k * 8 + tg];       af1[k][1] = A8[k * 8 + tg];
            af1[k][2] = A0[k * 8 + tg + 4];   af1[k][3] = A8[k * 8 + tg + 4];
            af2[k][0] = A0[16 + k * 8 + tg];     af2[k][1] = A8[16 + k * 8 + tg];
            af2[k][2] = A0[16 + k * 8 + tg + 4]; af2[k][3] = A8[16 + k * 8 + tg + 4];
        }
    }

    // ldmatrix per-thread offset: row = ((lane>>4)&1)*8 + (lane&7), col-half = (lane>>3)&1
    u32 lm_off = (u32)((((lane >> 4) & 1) * 8 + (lane & 7)) * (RSW * 4) + ((lane >> 3) & 1) * 16);

#define STAGE(T, BUF) do { \
    u32 _dst = sb + (u32)(BUF) * BUF_BYTES; \
    const char* _gs = (const char*)(g_bbf + (size_t)(vbase + (T) * TILE) * KB); \
    _Pragma("unroll") \
    for (int _p = 0; _p < 4; _p++) { \
        int _ch = tid + _p * 256; \
        int _row = _ch >> 3, _col = _ch & 7; \
        cpa16(_dst + (u32)(_row * (RSW * 4) + _col * 16), _gs + (size_t)_row * 128 + _col * 16); \
    } \
    if (tid < 32) cpa16(smem_u32(sE + ((T) & 3) * TILE) + (u32)tid * 16, \
                        (const char*)(g_esq2 + vbase + (T) * TILE) + tid * 16); \
    cpa_commit(); \
} while (0)

    STAGE(0, 0);
    STAGE(1, 1);

    float bd0 = 3.4e38f, bd1 = 3.4e38f, ss0 = 0.f, ss1 = 0.f;
    int bi0 = 0, bi1 = 0;
    int bufC = 0, bufS = 2;

    for (int i = 0; i < NTIL; i++) {
        cpa_wait<1>();            // group(i) complete (only group i+1 may pend)
        __syncthreads();          // all warps done with tile i-1 everywhere
        if (i + 2 < NTIL) STAGE(i + 2, bufS); else cpa_commit();

#pragma unroll
        for (int half = 0; half < 2; half++) {
            u32 bbase = sb + (u32)bufC * BUF_BYTES + (u32)(half * 64 * (RSW * 4)) + lm_off;
            float acc1[8][4], acc2[8][4];

#pragma unroll
            for (int nbp = 0; nbp < 4; nbp++) {
                u32 rowo = (u32)(nbp * 16 * (RSW * 4));
                u32 b0, b1, b2, b3;    // e1 k-step 0
                u32 c0, c1, c2, c3;    // e1 k-step 1
                u32 d0, d1, d2, d3;    // e2' k-step 0
                u32 e0, e1, e2, e3;    // e2' k-step 1
                ldm_x4(b0, b1, b2, b3, bbase + rowo);
                ldm_x4(c0, c1, c2, c3, bbase + rowo + 32);
                ldm_x4(d0, d1, d2, d3, bbase + rowo + 64);
                ldm_x4(e0, e1, e2, e3, bbase + rowo + 96);
                // acc1 = z1*e1
                mma16816_zc(acc1[2 * nbp],     af1[0], b0, b1);
                mma16816   (acc1[2 * nbp],     af1[1], c0, c1);
                mma16816_zc(acc1[2 * nbp + 1], af1[0], b2, b3);
                mma16816   (acc1[2 * nbp + 1], af1[1], c2, c3);
                // acc2 = z1*e2' + z2'*e1  (reuses e1 fragments)
                mma16816_zc(acc2[2 * nbp],     af1[0], d0, d1);
                mma16816   (acc2[2 * nbp],     af1[1], e0, e1);
                mma16816   (acc2[2 * nbp],     af2[0], b0, b1);
                mma16816   (acc2[2 * nbp],     af2[1], c0, c1);
                mma16816_zc(acc2[2 * nbp + 1], af1[0], d2, d3);
                mma16816   (acc2[2 * nbp + 1], af1[1], e2, e3);
                mma16816   (acc2[2 * nbp + 1], af2[0], b2, b3);
                mma16816   (acc2[2 * nbp + 1], af2[1], c2, c3);
            }

            // epilogue: u = acc1 + 2^-12*acc2 ; rows {g, g+8}, cols {c0, c0+1}
            const float* se = sE + (i & 3) * TILE + half * 64;
            int cb = vbase + i * TILE + half * 64 + 2 * tg;
#pragma unroll
            for (int nb = 0; nb < 8; nb++) {
                float2 e = *(const float2*)(se + nb * 8 + 2 * tg);
                int c0 = cb + nb * 8, c1 = c0 + 1;
                float u00 = fmaf(acc2[nb][0], RINV, acc1[nb][0]);
                float u01 = fmaf(acc2[nb][1], RINV, acc1[nb][1]);
                float u10 = fmaf(acc2[nb][2], RINV, acc1[nb][2]);
                float u11 = fmaf(acc2[nb][3], RINV, acc1[nb][3]);
                float d;
                d = fmaf(-2.f, u00, e.x); if (d < bd0) { bd0 = d; bi0 = c0; }
                d = fmaf(-2.f, u01, e.y); if (d < bd0) { bd0 = d; bi0 = c1; }
                d = fmaf(-2.f, u10, e.x); if (d < bd1) { bd1 = d; bi1 = c0; }
                d = fmaf(-2.f, u11, e.y); if (d < bd1) { bd1 = d; bi1 = c1; }
                ss0 += ex2f(u00) + ex2f(u01);
                ss1 += ex2f(u10) + ex2f(u11);
            }
        }

        bufC = (bufC == 2) ? 0 : bufC + 1;
        bufS = (bufS == 2) ? 0 : bufS + 1;
    }
#undef STAGE

    // reduce across the 4 threads of each row-group (quads), lexicographic
#pragma unroll
    for (int o = 1; o < 4; o <<= 1) {
        float od = __shfl_down_sync(~0u, bd0, o, 4);
        int   oi = __shfl_down_sync(~0u, bi0, o, 4);
        float os = __shfl_down_sync(~0u, ss0, o, 4);
        if (od < bd0 || (od == bd0 && oi < bi0)) { bd0 = od; bi0 = oi; }
        ss0 += os;
        od = __shfl_down_sync(~0u, bd1, o, 4);
        oi = __shfl_down_sync(~0u, bi1, o, 4);
        os = __shfl_down_sync(~0u, ss1, o, 4);
        if (od < bd1 || (od == bd1 && oi < bi1)) { bd1 = od; bi1 = oi; }
        ss1 += os;
    }
    if (tg == 0) {
        int sp = blockIdx.y;
        int o0 = (Rb + g) * VS + sp;
        int o1 = (Rb + g + 8) * VS + sp;
        g_pd[o0] = bd0; g_pi[o0] = bi0; g_ps[o0] = ss0;
        g_pd[o1] = bd1; g_pi[o1] = bi1; g_ps[o1] = ss1;
    }
}

// ---- kernel 3: merge 4 splits + losses + NCHW output (128 x 64) ------------
__global__ void vq_reduce(float* __restrict__ out) {
    int n = blockIdx.x * 64 + threadIdx.x;
    float4 pd = *(const float4*)(g_pd + n * VS);
    int4   pi = *(const int4*)(g_pi + n * VS);
    float4 ps = *(const float4*)(g_ps + n * VS);

    float bd = pd.x; int bi = pi.x;
    if (pd.y < bd || (pd.y == bd && pi.y < bi)) { bd = pd.y; bi = pi.y; }
    if (pd.z < bd || (pd.z == bd && pi.z < bi)) { bd = pd.z; bi = pi.z; }
    if (pd.w < bd || (pd.w == bd && pi.w < bi)) { bd = pd.w; bi = pi.w; }
    float S = ps.x + ps.y + ps.z + ps.w;
    float lse = lg2f(S) * LN2;

    const float4* ep = (const float4*)(g_en + (size_t)bi * C_DIM);
    const float4* zp = (const float4*)(g_zfn + (size_t)n * C_DIM);
    int b = n >> 10, hw = n & 1023;
    float* op = out + b * (C_DIM * 1024) + hw;
    float dot = 0.f, vq = 0.f;
#pragma unroll
    for (int i = 0; i < 8; i++) {
        float4 e = ep[i], zt = zp[i];
        dot = fmaf(e.x, zt.x, fmaf(e.y, zt.y, fmaf(e.z, zt.z, fmaf(e.w, zt.w, dot))));
        float dx = e.x - zt.x, dy = e.y - zt.y, dz = e.z - zt.z, dw = e.w - zt.w;
        vq = fmaf(dx, dx, fmaf(dy, dy, fmaf(dz, dz, fmaf(dw, dw, vq))));
        op[(4 * i + 0) * 1024] = e.x;
        op[(4 * i + 1) * 1024] = e.y;
        op[(4 * i + 2) * 1024] = e.z;
        op[(4 * i + 3) * 1024] = e.w;
    }
    float commit = lse - dot;

    __shared__ float sred[4];
    float v1 = vq, c1 = commit;
#pragma unroll
    for (int o = 16; o; o >>= 1) {
        v1 += __shfl_down_sync(~0u, v1, o);
        c1 += __shfl_down_sync(~0u, c1, o);
    }
    int wid = threadIdx.x >> 5, lid = threadIdx.x & 31;
    if (lid == 0) { sred[wid] = v1; sred[wid + 2] = c1; }
    __syncthreads();
    if (threadIdx.x == 0) {
        float vs = sred[0] + sred[1];
        float cs = sred[2] + sred[3];
        g_blk[blockIdx.x][0] = vs; g_blk[blockIdx.x][1] = cs;
        __threadfence();
        if (atomicAdd(&g_cnt, 1) == 127) {
            float va = 0.f, ca = 0.f;
            for (int i = 0; i < 128; i++) { va += g_blk[i][0]; ca += g_blk[i][1]; }
            out[N_TOK * C_DIM]     = va / (float)(N_TOK * C_DIM);
            out[N_TOK * C_DIM + 1] = 0.25f * (ca / (float)N_TOK);
            g_cnt = 0;
        }
    }
}

// ---------------------------------------------------------------------------
extern "C" void kernel_launch(void* const* d_in, const int* in_sizes, int n_in,
                              void* d_out, int out_size) {
    const float* z = (const float*)d_in[0];
    const float* emb = (const float*)d_in[1];
    if (n_in >= 2 && in_sizes[0] == V_CODES * C_DIM && in_sizes[1] == N_TOK * 8) {
        const float* t = z; z = emb; emb = t;
    }
    cudaFuncSetAttribute(vq_main, cudaFuncAttributeMaxDynamicSharedMemorySize, SMEM_DYN);
    prep<<<256, 256>>>(z, emb);
    dim3 grid(N_TOK / TOKB, YS);
    vq_main<<<grid, 256, SMEM_DYN>>>();
    vq_reduce<<<N_TOK / 64, 64>>>((float*)d_out);
    (void)out_size;
}

// round 17
// speedup vs baseline: 1.0924x; 1.0924x over previous
#include <cuda_runtime.h>
#include <cuda_fp16.h>
#include <cstdint>

// VectorQuantizer fwd: N=8192 tokens, V=8192 codes, C=32.
// S = zfn@en^T via mma.sync.m16n8k16 fp16, 3-product fp16 split:
//   u = z1e1 + 2^-12*( z1*(e2*2^12) + (z2*2^12)*e1 )  ~ fp32-exact
// B stores [e1 | e2'] (K=64); z2'*e1 reuses e1 ldmatrix frags; zero-C init.
// TILE=64, triple-buffer, 1 sync/tile (best R15 config). vq_reduce FUSED into
// vq_main's tail: last y-split block per x-group reduces its 128 tokens inline.

#define N_TOK 8192
#define V_CODES 8192
#define C_DIM 32
#define YS 4                    // grid.y splits
#define VS 4
#define VPB (V_CODES / YS)      // 2048 codes per block
#define TILE 64
#define NTIL (VPB / TILE)       // 32 tiles
#define TOKB 128
#define KA 32                   // u32 per A row: [z1 | z2'] fp16x2
#define KB 32                   // u32 per B row: [e1 | e2'] fp16x2
#define RSW 36                  // smem row stride in u32 (144B, bank-clean)
#define BUF_BYTES (TILE * RSW * 4)     // 9216
#define SMEM_DYN (3 * BUF_BYTES + 4 * TILE * 4 + 64)
#define L2E 1.4426950408889634f
#define LN2 0.6931471805599453f
#define L2EPS 1e-12f
#define RSCALE 4096.0f
#define RINV 0.000244140625f    // 2^-12

typedef unsigned int u32;

__device__ __align__(16) u32   g_abf[N_TOK * KA];    // A rows: [z1 | z2'] fp16x2
__device__ __align__(16) u32   g_bbf[V_CODES * KB];  // B rows: [e1 | e2'] fp16x2
__device__ __align__(16) float g_en[V_CODES * C_DIM];
__device__ __align__(16) float g_esq2[V_CODES];      // esq * log2e
__device__ __align__(16) float g_zfn[N_TOK * C_DIM];
__device__ float g_pd[N_TOK * VS];
__device__ int   g_pi[N_TOK * VS];
__device__ float g_ps[N_TOK * VS];
__device__ int   g_xcnt[64];    // per-x-group completion counters
__device__ float g_blk[64][2];
__device__ int   g_cnt;

__device__ __forceinline__ u32 smem_u32(const void* p) {
    u32 a;
    asm("{ .reg .u64 t; cvta.to.shared.u64 t, %1; cvt.u32.u64 %0, t; }" : "=r"(a) : "l"(p));
    return a;
}
__device__ __forceinline__ void cpa16(u32 s, const void* g) {
    asm volatile("cp.async.cg.shared.global [%0], [%1], 16;" :: "r"(s), "l"(g));
}
__device__ __forceinline__ void cpa_commit() { asm volatile("cp.async.commit_group;" ::: "memory"); }
template <int N> __device__ __forceinline__ void cpa_wait() {
    asm volatile("cp.async.wait_group %0;" :: "n"(N) : "memory");
}
__device__ __forceinline__ void ldm_x4(u32& r0, u32& r1, u32& r2, u32& r3, u32 addr) {
    asm volatile("ldmatrix.sync.aligned.m8n8.x4.shared.b16 {%0,%1,%2,%3}, [%4];"
                 : "=r"(r0), "=r"(r1), "=r"(r2), "=r"(r3) : "r"(addr));
}
// accumulate: D += A*B
__device__ __forceinline__ void mma16816(float* c, const u32* a, u32 b0, u32 b1) {
    asm volatile("mma.sync.aligned.m16n8k16.row.col.f32.f16.f16.f32 "
                 "{%0,%1,%2,%3}, {%4,%5,%6,%7}, {%8,%9}, {%0,%1,%2,%3};"
                 : "+f"(c[0]), "+f"(c[1]), "+f"(c[2]), "+f"(c[3])
                 : "r"(a[0]), "r"(a[1]), "r"(a[2]), "r"(a[3]), "r"(b0), "r"(b1));
}
// initialize: D = A*B (C = 0)
__device__ __forceinline__ void mma16816_zc(float* d, const u32* a, u32 b0, u32 b1) {
    asm volatile("mma.sync.aligned.m16n8k16.row.col.f32.f16.f16.f32 "
                 "{%0,%1,%2,%3}, {%4,%5,%6,%7}, {%8,%9}, {%10,%11,%12,%13};"
                 : "=f"(d[0]), "=f"(d[1]), "=f"(d[2]), "=f"(d[3])
                 : "r"(a[0]), "r"(a[1]), "r"(a[2]), "r"(a[3]), "r"(b0), "r"(b1),
                   "f"(0.f), "f"(0.f), "f"(0.f), "f"(0.f));
}
__device__ __forceinline__ float ex2f(float x) {
    float r; asm("ex2.approx.f32 %0, %1;" : "=f"(r) : "f"(x)); return r;
}
__device__ __forceinline__ float lg2f(float x) {
    float r; asm("lg2.approx.f32 %0, %1;" : "=f"(r) : "f"(x)); return r;
}
__device__ __forceinline__ u32 packh(__half a, __half b) {
    __half2 hh = __halves2half2(a, b);
    return *(u32*)&hh;
}

// ---- kernel 1: prep (256 blocks x 256 threads; 4 threads per row) ----------
__global__ void prep(const float* __restrict__ z, const float* __restrict__ emb) {
    int tid = threadIdx.x;
    int qt = tid & 3;            // quarter: channels qt*8 .. qt*8+7
    float vv[8];
    __half h1[8], h2[8];

    if (blockIdx.x < 128) {
        int r = blockIdx.x * 64 + (tid >> 2);
        const float4* src = (const float4*)(emb + r * C_DIM + qt * 8);
        float4 v0 = src[0], v1 = src[1];
        float ss = v0.x * v0.x + v0.y * v0.y + v0.z * v0.z + v0.w * v0.w
                 + v1.x * v1.x + v1.y * v1.y + v1.z * v1.z + v1.w * v1.w;
        ss += __shfl_xor_sync(~0u, ss, 1, 4);
        ss += __shfl_xor_sync(~0u, ss, 2, 4);
        float rcp = 1.0f / fmaxf(sqrtf(ss), L2EPS);
        vv[0] = v0.x * rcp; vv[1] = v0.y * rcp; vv[2] = v0.z * rcp; vv[3] = v0.w * rcp;
        vv[4] = v1.x * rcp; vv[5] = v1.y * rcp; vv[6] = v1.z * rcp; vv[7] = v1.w * rcp;
        float4* dst = (float4*)(g_en + r * C_DIM + qt * 8);
        dst[0] = make_float4(vv[0], vv[1], vv[2], vv[3]);
        dst[1] = make_float4(vv[4], vv[5], vv[6], vv[7]);
        float es = 0.f;
#pragma unroll
        for (int j = 0; j < 8; j++) es = fmaf(vv[j], vv[j], es);
        es += __shfl_xor_sync(~0u, es, 1, 4);
        es += __shfl_xor_sync(~0u, es, 2, 4);
        if (qt == 0) g_esq2[r] = es * L2E;
#pragma unroll
        for (int j = 0; j < 8; j++) {
            h1[j] = __float2half_rn(vv[j]);
            h2[j] = __float2half_rn((vv[j] - __half2float(h1[j])) * RSCALE);
        }
        const __half* segs[2] = { h1, h2 };           // B: e1 | e2'
        u32* brow = g_bbf + (size_t)r * KB + qt * 4;
#pragma unroll
        for (int s = 0; s < 2; s++)
#pragma unroll
            for (int p = 0; p < 4; p++)
                brow[s * 16 + p] = packh(segs[s][2 * p], segs[s][2 * p + 1]);
    } else {
        int n = (blockIdx.x - 128) * 64 + (tid >> 2);
        int b = n >> 10, hw = n & 1023;
        const float* zp = z + b * (C_DIM * 1024) + (qt * 8) * 1024 + hw;
        float ss = 0.f;
#pragma unroll
        for (int j = 0; j < 8; j++) { vv[j] = zp[j * 1024]; ss = fmaf(vv[j], vv[j], ss); }
        ss += __shfl_xor_sync(~0u, ss, 1, 4);
        ss += __shfl_xor_sync(~0u, ss, 2, 4);
        float rcp = 1.0f / fmaxf(sqrtf(ss), L2EPS);
        float4* dst = (float4*)(g_zfn + n * C_DIM + qt * 8);
        dst[0] = make_float4(vv[0] * rcp, vv[1] * rcp, vv[2] * rcp, vv[3] * rcp);
        dst[1] = make_float4(vv[4] * rcp, vv[5] * rcp, vv[6] * rcp, vv[7] * rcp);
        float rs = rcp * L2E;
#pragma unroll
        for (int j = 0; j < 8; j++) {
            float zs = vv[j] * rs;
            h1[j] = __float2half_rn(zs);
            h2[j] = __float2half_rn((zs - __half2float(h1[j])) * RSCALE);
        }
        const __half* segs[2] = { h1, h2 };           // A: z1 | z2'
        u32* arow = g_abf + (size_t)n * KA + qt * 4;
#pragma unroll
        for (int s = 0; s < 2; s++)
#pragma unroll
            for (int p = 0; p < 4; p++)
                arow[s * 16 + p] = packh(segs[s][2 * p], segs[s][2 * p + 1]);
    }
}

// ---- kernel 2: HMMA scan + fused per-x-group reduce ------------------------
// grid (64, 4), 256 threads, 2 CTAs/SM. 8 warps, warp = 16 token rows x 64 cols.
__global__ __launch_bounds__(256, 2) void vq_main(float* __restrict__ out) {
    extern __shared__ __align__(16) char dsm[];
    u32 sb = smem_u32(dsm);                      // [3][TILE*RSW] u32
    float* sE = (float*)(dsm + 3 * BUF_BYTES);   // [4][TILE]
    __shared__ int s_last;
    __shared__ float sred[8];

    int tid = threadIdx.x;
    int w = tid >> 5, lane = tid & 31;
    int g = lane >> 2, tg = lane & 3;
    int Rb = blockIdx.x * TOKB + w * 16;
    int vbase = blockIdx.y * VPB;

    // A fragments: z1 (k-steps 0,1) and z2' (k-steps 0,1), loaded once.
    u32 af1[2][4], af2[2][4];
    {
        const u32* A0 = g_abf + (size_t)(Rb + g) * KA;
        const u32* A8 = g_abf + (size_t)(Rb + g + 8) * KA;
#pragma unroll
        for (int k = 0; k < 2; k++) {
            af1[k][0] = A0[k * 8 + tg];       af1[k][1] = A8[k * 8 + tg];
            af1[k][2] = A0[k * 8 + tg + 4];   af1[k][3] = A8[k * 8 + tg + 4];
            af2[k][0] = A0[16 + k * 8 + tg];     af2[k][1] = A8[16 + k * 8 + tg];
            af2[k][2] = A0[16 + k * 8 + tg + 4]; af2[k][3] = A8[16 + k * 8 + tg + 4];
        }
    }

    // ldmatrix per-thread offset: row = ((lane>>4)&1)*8 + (lane&7), col-half = (lane>>3)&1
    u32 lm_off = (u32)((((lane >> 4) & 1) * 8 + (lane & 7)) * (RSW * 4) + ((lane >> 3) & 1) * 16);

#define STAGE(T, BUF) do { \
    u32 _dst = sb + (u32)(BUF) * BUF_BYTES; \
    const char* _gs = (const char*)(g_bbf + (size_t)(vbase + (T) * TILE) * KB); \
    _Pragma("unroll") \
    for (int _p = 0; _p < 2; _p++) { \
        int _ch = tid + _p * 256; \
        int _row = _ch >> 3, _col = _ch & 7; \
        cpa16(_dst + (u32)(_row * (RSW * 4) + _col * 16), _gs + (size_t)_row * 128 + _col * 16); \
    } \
    if (tid < 16) cpa16(smem_u32(sE + ((T) & 3) * TILE) + (u32)tid * 16, \
                        (const char*)(g_esq2 + vbase + (T) * TILE) + tid * 16); \
    cpa_commit(); \
} while (0)

    STAGE(0, 0);
    STAGE(1, 1);

    float bd0 = 3.4e38f, bd1 = 3.4e38f, ss0 = 0.f, ss1 = 0.f;
    int bi0 = 0, bi1 = 0;
    int bufC = 0, bufS = 2;

    for (int i = 0; i < NTIL; i++) {
        cpa_wait<1>();            // group(i) complete (only group i+1 may pend)
        __syncthreads();          // all warps done with tile i-1 everywhere
        if (i + 2 < NTIL) STAGE(i + 2, bufS); else cpa_commit();

        u32 bbase = sb + (u32)bufC * BUF_BYTES + lm_off;
        float acc1[8][4], acc2[8][4];

#pragma unroll
        for (int nbp = 0; nbp < 4; nbp++) {
            u32 rowo = (u32)(nbp * 16 * (RSW * 4));
            u32 b0, b1, b2, b3;    // e1 k-step 0
            u32 c0, c1, c2, c3;    // e1 k-step 1
            u32 d0, d1, d2, d3;    // e2' k-step 0
            u32 e0, e1, e2, e3;    // e2' k-step 1
            ldm_x4(b0, b1, b2, b3, bbase + rowo);
            ldm_x4(c0, c1, c2, c3, bbase + rowo + 32);
            ldm_x4(d0, d1, d2, d3, bbase + rowo + 64);
            ldm_x4(e0, e1, e2, e3, bbase + rowo + 96);
            // acc1 = z1*e1
            mma16816_zc(acc1[2 * nbp],     af1[0], b0, b1);
            mma16816   (acc1[2 * nbp],     af1[1], c0, c1);
            mma16816_zc(acc1[2 * nbp + 1], af1[0], b2, b3);
            mma16816   (acc1[2 * nbp + 1], af1[1], c2, c3);
            // acc2 = z1*e2' + z2'*e1  (reuses e1 fragments)
            mma16816_zc(acc2[2 * nbp],     af1[0], d0, d1);
            mma16816   (acc2[2 * nbp],     af1[1], e0, e1);
            mma16816   (acc2[2 * nbp],     af2[0], b0, b1);
            mma16816   (acc2[2 * nbp],     af2[1], c0, c1);
            mma16816_zc(acc2[2 * nbp + 1], af1[0], d2, d3);
            mma16816   (acc2[2 * nbp + 1], af1[1], e2, e3);
            mma16816   (acc2[2 * nbp + 1], af2[0], b2, b3);
            mma16816   (acc2[2 * nbp + 1], af2[1], c2, c3);
        }

        // epilogue: u = acc1 + 2^-12*acc2 ; rows {g, g+8}, cols {c0, c0+1}
        const float* se = sE + (i & 3) * TILE;
        int cb = vbase + i * TILE + 2 * tg;
#pragma unroll
        for (int nb = 0; nb < 8; nb++) {
            float2 e = *(const float2*)(se + nb * 8 + 2 * tg);
            int c0 = cb + nb * 8, c1 = c0 + 1;
            float u00 = fmaf(acc2[nb][0], RINV, acc1[nb][0]);
            float u01 = fmaf(acc2[nb][1], RINV, acc1[nb][1]);
            float u10 = fmaf(acc2[nb][2], RINV, acc1[nb][2]);
            float u11 = fmaf(acc2[nb][3], RINV, acc1[nb][3]);
            float d;
            d = fmaf(-2.f, u00, e.x); if (d < bd0) { bd0 = d; bi0 = c0; }
            d = fmaf(-2.f, u01, e.y); if (d < bd0) { bd0 = d; bi0 = c1; }
            d = fmaf(-2.f, u10, e.x); if (d < bd1) { bd1 = d; bi1 = c0; }
            d = fmaf(-2.f, u11, e.y); if (d < bd1) { bd1 = d; bi1 = c1; }
            ss0 += ex2f(u00) + ex2f(u01);
            ss1 += ex2f(u10) + ex2f(u11);
        }

        bufC = (bufC == 2) ? 0 : bufC + 1;
        bufS = (bufS == 2) ? 0 : bufS + 1;
    }
#undef STAGE

    // reduce across the 4 threads of each row-group (quads), lexicographic
#pragma unroll
    for (int o = 1; o < 4; o <<= 1) {
        float od = __shfl_down_sync(~0u, bd0, o, 4);
        int   oi = __shfl_down_sync(~0u, bi0, o, 4);
        float os = __shfl_down_sync(~0u, ss0, o, 4);
        if (od < bd0 || (od == bd0 && oi < bi0)) { bd0 = od; bi0 = oi; }
        ss0 += os;
        od = __shfl_down_sync(~0u, bd1, o, 4);
        oi = __shfl_down_sync(~0u, bi1, o, 4);
        os = __shfl_down_sync(~0u, ss1, o, 4);
        if (od < bd1 || (od == bd1 && oi < bi1)) { bd1 = od; bi1 = oi; }
        ss1 += os;
    }
    if (tg == 0) {
        int sp = blockIdx.y;
        int o0 = (Rb + g) * VS + sp;
        int o1 = (Rb + g + 8) * VS + sp;
        g_pd[o0] = bd0; g_pi[o0] = bi0; g_ps[o0] = ss0;
        g_pd[o1] = bd1; g_pi[o1] = bi1; g_ps[o1] = ss1;
    }

    // ---- fused reduce: last y-split block of this x-group finishes tokens --
    __syncthreads();
    if (tid == 0) {
        __threadfence();
        int t = atomicAdd(&g_xcnt[blockIdx.x], 1);
        s_last = (t == YS - 1);
        if (s_last) g_xcnt[blockIdx.x] = 0;    // reset for graph replay
    }
    __syncthreads();
    if (!s_last) return;

    float v1 = 0.f, c1 = 0.f;
    if (tid < TOKB) {
        int n = blockIdx.x * TOKB + tid;
        float4 pd = *(const float4*)(g_pd + n * VS);
        int4   pi = *(const int4*)(g_pi + n * VS);
        float4 ps = *(const float4*)(g_ps + n * VS);

        float bd = pd.x; int bi = pi.x;
        if (pd.y < bd || (pd.y == bd && pi.y < bi)) { bd = pd.y; bi = pi.y; }
        if (pd.z < bd || (pd.z == bd && pi.z < bi)) { bd = pd.z; bi = pi.z; }
        if (pd.w < bd || (pd.w == bd && pi.w < bi)) { bd = pd.w; bi = pi.w; }
        float S = ps.x + ps.y + ps.z + ps.w;
        float lse = lg2f(S) * LN2;

        const float4* ep = (const float4*)(g_en + (size_t)bi * C_DIM);
        const float4* zp = (const float4*)(g_zfn + (size_t)n * C_DIM);
        int b = n >> 10, hw = n & 1023;
        float* op = out + b * (C_DIM * 1024) + hw;
        float dot = 0.f, vq = 0.f;
#pragma unroll
        for (int i = 0; i < 8; i++) {
            float4 e = ep[i], zt = zp[i];
            dot = fmaf(e.x, zt.x, fmaf(e.y, zt.y, fmaf(e.z, zt.z, fmaf(e.w, zt.w, dot))));
            float dx = e.x - zt.x, dy = e.y - zt.y, dz = e.z - zt.z, dw = e.w - zt.w;
            vq = fmaf(dx, dx, fmaf(dy, dy, fmaf(dz, dz, fmaf(dw, dw, vq))));
            op[(4 * i + 0) * 1024] = e.x;
            op[(4 * i + 1) * 1024] = e.y;
            op[(4 * i + 2) * 1024] = e.z;
            op[(4 * i + 3) * 1024] = e.w;
        }
        v1 = vq;
        c1 = lse - dot;
    }

#pragma unroll
    for (int o = 16; o; o >>= 1) {
        v1 += __shfl_down_sync(~0u, v1, o);
        c1 += __shfl_down_sync(~0u, c1, o);
    }
    if (lane == 0) { sred[w] = v1; }
    __syncthreads();
    if (lane == 0 && w < 4) { /* c-part second pass via smem reuse */ }
    // store commit partials after the vq slots
    if (lane == 0) { sred[w] = v1; }
    __syncthreads();
    // simple: redo with both arrays in one pass
    if (tid == 0) {
        float vs = sred[0] + sred[1] + sred[2] + sred[3];
        // commit sums: recompute via shuffle results stored below
        g_blk[blockIdx.x][0] = vs;
    }
    __syncthreads();
    if (lane == 0) { sred[w] = c1; }
    __syncthreads();
    if (tid == 0) {
        float cs = sred[0] + sred[1] + sred[2] + sred[3];
        g_blk[blockIdx.x][1] = cs;
        __threadfence();
        if (atomicAdd(&g_cnt, 1) == 63) {
            float va = 0.f, ca = 0.f;
            for (int i = 0; i < 64; i++) { va += g_blk[i][0]; ca += g_blk[i][1]; }
            out[N_TOK * C_DIM]     = va / (float)(N_TOK * C_DIM);
            out[N_TOK * C_DIM + 1] = 0.25f * (ca / (float)N_TOK);
            g_cnt = 0;
        }
    }
}

// ---------------------------------------------------------------------------
extern "C" void kernel_launch(void* const* d_in, const int* in_sizes, int n_in,
                              void* d_out, int out_size) {
    const float* z = (const float*)d_in[0];
    const float* emb = (const float*)d_in[1];
    if (n_in >= 2 && in_sizes[0] == V_CODES * C_DIM && in_sizes[1] == N_TOK * 8) {
        const float* t = z; z = emb; emb = t;
    }
    cudaFuncSetAttribute(vq_main, cudaFuncAttributeMaxDynamicSharedMemorySize, SMEM_DYN);
    prep<<<256, 256>>>(z, emb);
    dim3 grid(N_TOK / TOKB, YS);
    vq_main<<<grid, 256, SMEM_DYN>>>((float*)d_out);
    (void)out_size;
}